// round 2
// baseline (speedup 1.0000x reference)
#include <cuda_runtime.h>
#include <math.h>

// ---------------- problem constants ----------------
#define BATCH 16
#define HH    56
#define WW    56
#define DIM   384
#define NHEAD 12
#define DHEAD 32
#define FFDIM 1536
#define WSZ   8
#define HW    (HH*WW)            // 3136
#define NTOK  (BATCH*HW)         // 50176
#define NWIN  ((HH/WSZ)*(WW/WSZ))// 49 windows per image
#define LRED  49                 // reduced tokens per image
#define QKVD  (3*NHEAD*DHEAD)    // 1152
#define ATTN_SCALE 0.17677669529663687f  // 1/sqrt(32)
#define LN_EPS 1e-6f

// ---------------- scratch (no allocations allowed) ----------------
__device__ float g_ln [(size_t)NTOK * DIM];
__device__ float g_big[(size_t)NTOK * FFDIM];   // qkv (1152) / ffn hidden (1536)
__device__ float g_tmp[(size_t)NTOK * DIM];     // attention outputs
__device__ float g_q  [(size_t)NTOK * DIM];
__device__ float g_r  [(size_t)BATCH * LRED * DIM];
__device__ float g_kv [(size_t)BATCH * LRED * 2 * DIM];

// ---------------- LayerNorm: one warp per row (DIM=384 = 96 float4) ----------------
__global__ void ln_kernel(const float* __restrict__ x, const float* __restrict__ g,
                          const float* __restrict__ b, float* __restrict__ y, int M)
{
    int row  = blockIdx.x * 8 + (threadIdx.x >> 5);
    int lane = threadIdx.x & 31;
    if (row >= M) return;
    const float4* xr = (const float4*)(x + (size_t)row * DIM);
    float4 v0 = xr[lane], v1 = xr[lane + 32], v2 = xr[lane + 64];

    float s = v0.x+v0.y+v0.z+v0.w + v1.x+v1.y+v1.z+v1.w + v2.x+v2.y+v2.z+v2.w;
    #pragma unroll
    for (int o = 16; o; o >>= 1) s += __shfl_xor_sync(0xFFFFFFFFu, s, o);
    float mean = s * (1.0f / DIM);

    float vs = 0.f;
    {
        float d;
        d=v0.x-mean; vs+=d*d; d=v0.y-mean; vs+=d*d; d=v0.z-mean; vs+=d*d; d=v0.w-mean; vs+=d*d;
        d=v1.x-mean; vs+=d*d; d=v1.y-mean; vs+=d*d; d=v1.z-mean; vs+=d*d; d=v1.w-mean; vs+=d*d;
        d=v2.x-mean; vs+=d*d; d=v2.y-mean; vs+=d*d; d=v2.z-mean; vs+=d*d; d=v2.w-mean; vs+=d*d;
    }
    #pragma unroll
    for (int o = 16; o; o >>= 1) vs += __shfl_xor_sync(0xFFFFFFFFu, vs, o);
    float rstd = rsqrtf(vs * (1.0f / DIM) + LN_EPS);

    const float4* gr = (const float4*)g;
    const float4* br = (const float4*)b;
    float4* yr = (float4*)(y + (size_t)row * DIM);
    #pragma unroll
    for (int c = 0; c < 3; c++) {
        float4 xv = (c==0)?v0:((c==1)?v1:v2);
        float4 gv = gr[lane + c*32], bv = br[lane + c*32], ov;
        ov.x = (xv.x - mean) * rstd * gv.x + bv.x;
        ov.y = (xv.y - mean) * rstd * gv.y + bv.y;
        ov.z = (xv.z - mean) * rstd * gv.z + bv.z;
        ov.w = (xv.w - mean) * rstd * gv.w + bv.w;
        yr[lane + c*32] = ov;
    }
}

// ---------------- GEMM: C[M,N] = A[M,K] @ B[K,N] (+bias)(+silu | +residual) --------
// MODE 0: A row-major [M,K].  MODE 1: A gathered from g_ln for the 8x8-stride conv
//          (row m = (b, hs, ws) reduced token; k = (i*8+j)*384+cin -> contiguous per i).
// EPI 0: +bias (if non-null). EPI 1: +bias then SiLU. EPI 2: +bias then +res[row*N+col].
// Tiles: BM=128, BN=64, BK=16, 256 threads, 8x4 per-thread accumulators.
template<int MODE, int EPI>
__global__ void gemm_kernel(const float* __restrict__ A, const float* __restrict__ B,
                            const float* __restrict__ bias, const float* __restrict__ res,
                            float* __restrict__ C, int M, int N, int K)
{
    __shared__ float As[16][129];   // [k][m], padded
    __shared__ float Bs[16][64];    // [k][n]
    const int t   = threadIdx.x;          // 256
    const int ty  = t >> 4, tx = t & 15;
    const int row0 = blockIdx.y * 128;
    const int col0 = blockIdx.x * 64;

    float acc[8][4];
    #pragma unroll
    for (int i = 0; i < 8; i++)
        #pragma unroll
        for (int j = 0; j < 4; j++) acc[i][j] = 0.f;

    for (int k0 = 0; k0 < K; k0 += 16) {
        // --- load A tile: 128x16 = 512 float4, 2 per thread ---
        #pragma unroll
        for (int r = 0; r < 2; r++) {
            int f  = t + r * 256;
            int ar = f >> 2;              // 0..127
            int ak = (f & 3) * 4;         // 0,4,8,12
            int grow = row0 + ar;
            float4 av = make_float4(0.f, 0.f, 0.f, 0.f);
            if (grow < M) {
                size_t idx;
                if (MODE == 0) {
                    idx = (size_t)grow * K + (k0 + ak);
                } else {
                    int bb = grow / 49, wq = grow % 49;
                    int hs = wq / 7,    ws = wq % 7;
                    int kk = k0 + ak;
                    int i  = kk / 3072;          // window row (never crosses within a float4)
                    int rem = kk % 3072;         // (j,cin), contiguous in memory
                    idx = ((size_t)((bb * HH + hs * 8 + i) * WW + ws * 8)) * DIM + rem;
                }
                av = *(const float4*)(A + idx);
            }
            As[ak + 0][ar] = av.x;
            As[ak + 1][ar] = av.y;
            As[ak + 2][ar] = av.z;
            As[ak + 3][ar] = av.w;
        }
        // --- load B tile: 16x64 = 256 float4, 1 per thread ---
        {
            int kr = t >> 4, nq = (t & 15) * 4;
            float4 bv = *(const float4*)(B + (size_t)(k0 + kr) * N + col0 + nq);
            *(float4*)&Bs[kr][nq] = bv;
        }
        __syncthreads();

        #pragma unroll
        for (int kk = 0; kk < 16; kk++) {
            float a[8];
            #pragma unroll
            for (int i = 0; i < 8; i++) a[i] = As[kk][ty * 8 + i];
            float4 b4 = *(const float4*)&Bs[kk][tx * 4];
            float bb[4] = {b4.x, b4.y, b4.z, b4.w};
            #pragma unroll
            for (int i = 0; i < 8; i++)
                #pragma unroll
                for (int j = 0; j < 4; j++) acc[i][j] += a[i] * bb[j];
        }
        __syncthreads();
    }

    // --- epilogue ---
    const int col = col0 + tx * 4;
    float4 bi = make_float4(0.f, 0.f, 0.f, 0.f);
    if (bias) bi = *(const float4*)(bias + col);
    #pragma unroll
    for (int i = 0; i < 8; i++) {
        int grow = row0 + ty * 8 + i;
        if (grow >= M) continue;
        float4 v;
        v.x = acc[i][0] + bi.x; v.y = acc[i][1] + bi.y;
        v.z = acc[i][2] + bi.z; v.w = acc[i][3] + bi.w;
        if (EPI == 1) {
            v.x = v.x / (1.f + __expf(-v.x));
            v.y = v.y / (1.f + __expf(-v.y));
            v.z = v.z / (1.f + __expf(-v.z));
            v.w = v.w / (1.f + __expf(-v.w));
        }
        if (EPI == 2) {
            float4 r4 = *(const float4*)(res + (size_t)grow * N + col);
            v.x += r4.x; v.y += r4.y; v.z += r4.z; v.w += r4.w;
        }
        *(float4*)(C + (size_t)grow * N + col) = v;
    }
}

// ---------------- local window attention: block = (window, head), 64 threads -------
__global__ void winattn_kernel(const float* __restrict__ qkv, float* __restrict__ out)
{
    const int blk = blockIdx.x;           // 784*12
    const int h   = blk % NHEAD;
    const int win = blk / NHEAD;
    const int bb  = win / 49;
    const int wq  = win % 49;
    const int hs  = wq / 7, ws = wq % 7;

    __shared__ float ks[64][32], vs[64][32];
    const int tid = threadIdx.x;          // 64 = one query per thread
    const int iy = tid >> 3, ix = tid & 7;
    const int tok = (bb * HH + hs * 8 + iy) * WW + ws * 8 + ix;
    const float* base = qkv + (size_t)tok * QKVD + h * DHEAD;

    float q[32];
    #pragma unroll
    for (int d4 = 0; d4 < 8; d4++) {
        float4 qv = *(const float4*)(base + d4 * 4);
        q[d4*4+0]=qv.x; q[d4*4+1]=qv.y; q[d4*4+2]=qv.z; q[d4*4+3]=qv.w;
        *(float4*)&ks[tid][d4*4] = *(const float4*)(base + 384 + d4 * 4);
        *(float4*)&vs[tid][d4*4] = *(const float4*)(base + 768 + d4 * 4);
    }
    __syncthreads();

    float m = -1e30f, ssum = 0.f, acc[32];
    #pragma unroll
    for (int d = 0; d < 32; d++) acc[d] = 0.f;

    for (int l = 0; l < 64; l++) {
        float s0=0.f, s1=0.f, s2=0.f, s3=0.f;
        #pragma unroll
        for (int d = 0; d < 32; d += 4) {
            s0 += q[d+0]*ks[l][d+0]; s1 += q[d+1]*ks[l][d+1];
            s2 += q[d+2]*ks[l][d+2]; s3 += q[d+3]*ks[l][d+3];
        }
        float s = (s0+s1+s2+s3) * ATTN_SCALE;
        float mn = fmaxf(m, s);
        float corr = __expf(m - mn);
        float p    = __expf(s - mn);
        ssum = ssum * corr + p;
        #pragma unroll
        for (int d = 0; d < 32; d++) acc[d] = acc[d] * corr + p * vs[l][d];
        m = mn;
    }
    float inv = 1.f / ssum;
    float* o = out + (size_t)tok * DIM + h * DHEAD;
    #pragma unroll
    for (int d4 = 0; d4 < 8; d4++) {
        float4 v;
        v.x = acc[d4*4+0]*inv; v.y = acc[d4*4+1]*inv;
        v.z = acc[d4*4+2]*inv; v.w = acc[d4*4+3]*inv;
        *(float4*)(o + d4 * 4) = v;
    }
}

// ---------------- global attention: block = (batch, head), K=49 in SMEM ------------
__global__ void gattn_kernel(const float* __restrict__ q, const float* __restrict__ kv,
                             float* __restrict__ out)
{
    const int bb = blockIdx.x / NHEAD;
    const int h  = blockIdx.x % NHEAD;
    __shared__ float ks[49][32], vs[49][32];
    const int tid = threadIdx.x;          // 256

    for (int e = tid; e < 49 * 32; e += 256) {
        int l = e >> 5, d = e & 31;
        size_t r = ((size_t)(bb * LRED + l)) * (2 * DIM) + h * DHEAD + d;
        ks[l][d] = kv[r];
        vs[l][d] = kv[r + DIM];
    }
    __syncthreads();

    for (int qi = tid; qi < HW; qi += 256) {
        const int tok = bb * HW + qi;
        const float* qp = q + (size_t)tok * DIM + h * DHEAD;
        float qr[32];
        #pragma unroll
        for (int d4 = 0; d4 < 8; d4++) {
            float4 qv = *(const float4*)(qp + d4 * 4);
            qr[d4*4+0]=qv.x; qr[d4*4+1]=qv.y; qr[d4*4+2]=qv.z; qr[d4*4+3]=qv.w;
        }
        float m = -1e30f, ssum = 0.f, acc[32];
        #pragma unroll
        for (int d = 0; d < 32; d++) acc[d] = 0.f;

        for (int l = 0; l < 49; l++) {
            float s0=0.f, s1=0.f, s2=0.f, s3=0.f;
            #pragma unroll
            for (int d = 0; d < 32; d += 4) {
                s0 += qr[d+0]*ks[l][d+0]; s1 += qr[d+1]*ks[l][d+1];
                s2 += qr[d+2]*ks[l][d+2]; s3 += qr[d+3]*ks[l][d+3];
            }
            float s = (s0+s1+s2+s3) * ATTN_SCALE;
            float mn = fmaxf(m, s);
            float corr = __expf(m - mn);
            float p    = __expf(s - mn);
            ssum = ssum * corr + p;
            #pragma unroll
            for (int d = 0; d < 32; d++) acc[d] = acc[d] * corr + p * vs[l][d];
            m = mn;
        }
        float inv = 1.f / ssum;
        float* o = out + (size_t)tok * DIM + h * DHEAD;
        #pragma unroll
        for (int d4 = 0; d4 < 8; d4++) {
            float4 v;
            v.x = acc[d4*4+0]*inv; v.y = acc[d4*4+1]*inv;
            v.z = acc[d4*4+2]*inv; v.w = acc[d4*4+3]*inv;
            *(float4*)(o + d4 * 4) = v;
        }
    }
}

// ---------------- launch ----------------
static inline dim3 ggrid(int M, int N) { return dim3(N / 64, (M + 127) / 128); }

extern "C" void kernel_launch(void* const* d_in, const int* in_sizes, int n_in,
                              void* d_out, int out_size)
{
    const float* x      = (const float*)d_in[0];
    const float* g1     = (const float*)d_in[1];
    const float* be1    = (const float*)d_in[2];
    const float* w_qkv  = (const float*)d_in[3];
    const float* b_qkv  = (const float*)d_in[4];
    const float* w_lo   = (const float*)d_in[5];
    const float* b_lo   = (const float*)d_in[6];
    const float* g2     = (const float*)d_in[7];
    const float* be2    = (const float*)d_in[8];
    const float* w_f1l  = (const float*)d_in[9];
    const float* b_f1l  = (const float*)d_in[10];
    const float* w_f2l  = (const float*)d_in[11];
    const float* b_f2l  = (const float*)d_in[12];
    const float* g3     = (const float*)d_in[13];
    const float* be3    = (const float*)d_in[14];
    const float* w_q    = (const float*)d_in[15];
    const float* w_kv   = (const float*)d_in[16];
    const float* conv_w = (const float*)d_in[17];
    const float* conv_b = (const float*)d_in[18];
    const float* w_go   = (const float*)d_in[19];
    const float* b_go   = (const float*)d_in[20];
    const float* g4     = (const float*)d_in[21];
    const float* be4    = (const float*)d_in[22];
    const float* w_f1g  = (const float*)d_in[23];
    const float* b_f1g  = (const float*)d_in[24];
    const float* w_f2g  = (const float*)d_in[25];
    const float* b_f2g  = (const float*)d_in[26];
    float* out = (float*)d_out;

    // Resolve scratch addresses every call (no static caching — harness rule).
    float *p_ln, *p_big, *p_tmp, *p_q, *p_r, *p_kv;
    cudaGetSymbolAddress((void**)&p_ln,  g_ln);
    cudaGetSymbolAddress((void**)&p_big, g_big);
    cudaGetSymbolAddress((void**)&p_tmp, g_tmp);
    cudaGetSymbolAddress((void**)&p_q,   g_q);
    cudaGetSymbolAddress((void**)&p_r,   g_r);
    cudaGetSymbolAddress((void**)&p_kv,  g_kv);

    // ---- block 1: local attention ----
    ln_kernel<<<NTOK / 8, 256>>>(x, g1, be1, p_ln, NTOK);
    gemm_kernel<0,0><<<ggrid(NTOK, QKVD), 256>>>(p_ln, w_qkv, b_qkv, nullptr, p_big, NTOK, QKVD, DIM);
    winattn_kernel<<<BATCH * NWIN * NHEAD, 64>>>(p_big, p_tmp);
    gemm_kernel<0,2><<<ggrid(NTOK, DIM), 256>>>(p_tmp, w_lo, b_lo, x, out, NTOK, DIM, DIM);

    // ---- block 2: local FFN ----
    ln_kernel<<<NTOK / 8, 256>>>(out, g2, be2, p_ln, NTOK);
    gemm_kernel<0,1><<<ggrid(NTOK, FFDIM), 256>>>(p_ln, w_f1l, b_f1l, nullptr, p_big, NTOK, FFDIM, DIM);
    gemm_kernel<0,2><<<ggrid(NTOK, DIM), 256>>>(p_big, w_f2l, b_f2l, out, out, NTOK, DIM, FFDIM);

    // ---- block 3: global attention ----
    ln_kernel<<<NTOK / 8, 256>>>(out, g3, be3, p_ln, NTOK);
    gemm_kernel<0,0><<<ggrid(NTOK, DIM), 256>>>(p_ln, w_q, nullptr, nullptr, p_q, NTOK, DIM, DIM);
    // strided 8x8 conv as gather-GEMM: M=784 reduced tokens, K=64*384
    gemm_kernel<1,0><<<ggrid(BATCH * LRED, DIM), 256>>>(p_ln, conv_w, conv_b, nullptr, p_r,
                                                        BATCH * LRED, DIM, WSZ * WSZ * DIM);
    gemm_kernel<0,0><<<ggrid(BATCH * LRED, 2 * DIM), 256>>>(p_r, w_kv, nullptr, nullptr, p_kv,
                                                            BATCH * LRED, 2 * DIM, DIM);
    gattn_kernel<<<BATCH * NHEAD, 256>>>(p_q, p_kv, p_tmp);
    gemm_kernel<0,2><<<ggrid(NTOK, DIM), 256>>>(p_tmp, w_go, b_go, out, out, NTOK, DIM, DIM);

    // ---- block 4: global FFN ----
    ln_kernel<<<NTOK / 8, 256>>>(out, g4, be4, p_ln, NTOK);
    gemm_kernel<0,1><<<ggrid(NTOK, FFDIM), 256>>>(p_ln, w_f1g, b_f1g, nullptr, p_big, NTOK, FFDIM, DIM);
    gemm_kernel<0,2><<<ggrid(NTOK, DIM), 256>>>(p_big, w_f2g, b_f2g, out, out, NTOK, DIM, FFDIM);
}

// round 3
// speedup vs baseline: 2.7827x; 2.7827x over previous
#include <cuda_runtime.h>
#include <math.h>
#include <stdint.h>

// ---------------- problem constants ----------------
#define BATCH 16
#define HH    56
#define WW    56
#define DIM   384
#define NHEAD 12
#define DHEAD 32
#define FFDIM 1536
#define WSZ   8
#define HW    (HH*WW)            // 3136
#define NTOK  (BATCH*HW)         // 50176
#define LRED  49                 // reduced tokens per image
#define QKVD  (3*NHEAD*DHEAD)    // 1152
#define ATTN_SCALE 0.17677669529663687f  // 1/sqrt(32)
#define LN_EPS 1e-6f
#define CONV_K (WSZ*WSZ*DIM)     // 24576
#define CONV_SPLIT 8
#define CONV_M (BATCH*LRED)      // 784

// ---------------- scratch (no allocations allowed) ----------------
__device__ float g_ln   [(size_t)NTOK * DIM];
__device__ float g_big  [(size_t)NTOK * FFDIM];
__device__ float g_tmp  [(size_t)NTOK * DIM];
__device__ float g_q    [(size_t)NTOK * DIM];
__device__ float g_r    [(size_t)CONV_M * DIM];
__device__ float g_kv   [(size_t)CONV_M * 2 * DIM];
__device__ float g_rpart[(size_t)CONV_SPLIT * CONV_M * DIM];

// ---------------- helpers ----------------
__device__ __forceinline__ uint32_t f2tf32(float x) {
    uint32_t r; asm("cvt.rna.tf32.f32 %0, %1;" : "=r"(r) : "f"(x)); return r;
}
__device__ __forceinline__ void mma_tf32(float* c, const uint32_t* a, const uint32_t* b) {
    asm volatile("mma.sync.aligned.m16n8k8.row.col.f32.tf32.tf32.f32 "
        "{%0,%1,%2,%3}, {%4,%5,%6,%7}, {%8,%9}, {%0,%1,%2,%3};"
        : "+f"(c[0]), "+f"(c[1]), "+f"(c[2]), "+f"(c[3])
        : "r"(a[0]), "r"(a[1]), "r"(a[2]), "r"(a[3]), "r"(b[0]), "r"(b[1]));
}

// ---------------- LayerNorm: one warp per row ----------------
__global__ void ln_kernel(const float* __restrict__ x, const float* __restrict__ g,
                          const float* __restrict__ b, float* __restrict__ y, int M)
{
    int row  = blockIdx.x * 8 + (threadIdx.x >> 5);
    int lane = threadIdx.x & 31;
    if (row >= M) return;
    const float4* xr = (const float4*)(x + (size_t)row * DIM);
    float4 v0 = xr[lane], v1 = xr[lane + 32], v2 = xr[lane + 64];

    float s = v0.x+v0.y+v0.z+v0.w + v1.x+v1.y+v1.z+v1.w + v2.x+v2.y+v2.z+v2.w;
    #pragma unroll
    for (int o = 16; o; o >>= 1) s += __shfl_xor_sync(0xFFFFFFFFu, s, o);
    float mean = s * (1.0f / DIM);

    float vs = 0.f;
    {
        float d;
        d=v0.x-mean; vs+=d*d; d=v0.y-mean; vs+=d*d; d=v0.z-mean; vs+=d*d; d=v0.w-mean; vs+=d*d;
        d=v1.x-mean; vs+=d*d; d=v1.y-mean; vs+=d*d; d=v1.z-mean; vs+=d*d; d=v1.w-mean; vs+=d*d;
        d=v2.x-mean; vs+=d*d; d=v2.y-mean; vs+=d*d; d=v2.z-mean; vs+=d*d; d=v2.w-mean; vs+=d*d;
    }
    #pragma unroll
    for (int o = 16; o; o >>= 1) vs += __shfl_xor_sync(0xFFFFFFFFu, vs, o);
    float rstd = rsqrtf(vs * (1.0f / DIM) + LN_EPS);

    const float4* gr = (const float4*)g;
    const float4* br = (const float4*)b;
    float4* yr = (float4*)(y + (size_t)row * DIM);
    #pragma unroll
    for (int c = 0; c < 3; c++) {
        float4 xv = (c==0)?v0:((c==1)?v1:v2);
        float4 gv = gr[lane + c*32], bv = br[lane + c*32], ov;
        ov.x = (xv.x - mean) * rstd * gv.x + bv.x;
        ov.y = (xv.y - mean) * rstd * gv.y + bv.y;
        ov.z = (xv.z - mean) * rstd * gv.z + bv.z;
        ov.w = (xv.w - mean) * rstd * gv.w + bv.w;
        yr[lane + c*32] = ov;
    }
}

// ---------------- tf32 tensor-core GEMM -------------------------------------
// C[M,N] = A[M,K] @ B[K,N], tiles 128x128x16, 256 threads (8 warps 2x4),
// warp tile 64x32 = 4x4 m16n8 frags, mma.m16n8k8.tf32, fp32 accumulate.
// MODE 0: A row-major.  MODE 1: A gathered for the 8x8-stride conv.
// EPI 0: +bias. EPI 1: +bias,SiLU. EPI 2: +bias,+res. EPI 3: split-K partial
//        (C += blockIdx.z*M*N, K range = [z*kChunk, (z+1)*kChunk), no bias).
template<int MODE, int EPI>
__global__ __launch_bounds__(256, 2)
void gemm_tc(const float* __restrict__ A, const float* __restrict__ B,
             const float* __restrict__ bias, const float* __restrict__ res,
             float* __restrict__ C, int M, int N, int K, int kChunk)
{
    __shared__ uint32_t As[128][20];   // [m][k], pitch 20: conflict-free frag loads
    __shared__ uint32_t Bs[16][136];   // [k][n], pitch 136

    const int t    = threadIdx.x;
    const int lane = t & 31, wid = t >> 5;
    const int gid  = lane >> 2, tig = lane & 3;
    const int wm   = wid >> 2,  wn  = wid & 3;
    const int row0 = blockIdx.y * 128, col0 = blockIdx.x * 128;

    const int kbeg = (EPI == 3) ? blockIdx.z * kChunk : 0;
    const int kend = (EPI == 3) ? kbeg + kChunk : K;
    if (EPI == 3) C += (size_t)blockIdx.z * M * N;

    // gmem load coordinates (2 float4 each for A and B per thread)
    const int a_ar0 = (t      ) >> 2, a_ak0 = ((t      ) & 3) * 4;
    const int a_ar1 = (t + 256) >> 2, a_ak1 = ((t + 256) & 3) * 4;
    const int b_kr0 = (t      ) >> 5, b_nq0 = ((t      ) & 31) * 4;
    const int b_kr1 = (t + 256) >> 5, b_nq1 = ((t + 256) & 31) * 4;

    float acc[4][4][4] = {};
    float4 pa0, pa1, pb0, pb1;

    // ---- gmem tile load into registers ----
    #define LOAD_A(dst, ar, ak, k0)                                              \
        {                                                                        \
            int grow = row0 + (ar);                                              \
            dst = make_float4(0.f, 0.f, 0.f, 0.f);                               \
            if (grow < M) {                                                      \
                size_t idx;                                                      \
                if (MODE == 0) idx = (size_t)grow * K + ((k0) + (ak));           \
                else {                                                           \
                    int bb = grow / 49, wq = grow % 49;                          \
                    int hs = wq / 7,   ws = wq % 7;                              \
                    int kk = (k0) + (ak);                                        \
                    int i  = kk / 3072;                                          \
                    int rem = kk % 3072;                                         \
                    idx = ((size_t)((bb * HH + hs * 8 + i) * WW + ws * 8)) * DIM + rem; \
                }                                                                \
                dst = *(const float4*)(A + idx);                                 \
            }                                                                    \
        }
    #define LOAD_B(dst, kr, nq, k0)                                              \
        dst = *(const float4*)(B + (size_t)((k0) + (kr)) * N + col0 + (nq));

    #define STORE_TILES()                                                        \
        {                                                                        \
            *(uint4*)&As[a_ar0][a_ak0] = make_uint4(f2tf32(pa0.x), f2tf32(pa0.y),\
                                                    f2tf32(pa0.z), f2tf32(pa0.w));\
            *(uint4*)&As[a_ar1][a_ak1] = make_uint4(f2tf32(pa1.x), f2tf32(pa1.y),\
                                                    f2tf32(pa1.z), f2tf32(pa1.w));\
            *(uint4*)&Bs[b_kr0][b_nq0] = make_uint4(f2tf32(pb0.x), f2tf32(pb0.y),\
                                                    f2tf32(pb0.z), f2tf32(pb0.w));\
            *(uint4*)&Bs[b_kr1][b_nq1] = make_uint4(f2tf32(pb1.x), f2tf32(pb1.y),\
                                                    f2tf32(pb1.z), f2tf32(pb1.w));\
        }

    // prologue
    LOAD_A(pa0, a_ar0, a_ak0, kbeg); LOAD_A(pa1, a_ar1, a_ak1, kbeg);
    LOAD_B(pb0, b_kr0, b_nq0, kbeg); LOAD_B(pb1, b_kr1, b_nq1, kbeg);
    STORE_TILES();
    __syncthreads();

    for (int k0 = kbeg + 16; k0 <= kend; k0 += 16) {
        if (k0 < kend) {
            LOAD_A(pa0, a_ar0, a_ak0, k0); LOAD_A(pa1, a_ar1, a_ak1, k0);
            LOAD_B(pb0, b_kr0, b_nq0, k0); LOAD_B(pb1, b_kr1, b_nq1, k0);
        }
        // ---- compute on current smem tile ----
        #pragma unroll
        for (int kc = 0; kc < 2; kc++) {
            uint32_t af[4][4];
            #pragma unroll
            for (int mt = 0; mt < 4; mt++) {
                int r = wm * 64 + mt * 16 + gid;
                int c = kc * 8 + tig;
                af[mt][0] = As[r    ][c    ];
                af[mt][1] = As[r + 8][c    ];
                af[mt][2] = As[r    ][c + 4];
                af[mt][3] = As[r + 8][c + 4];
            }
            uint32_t bf[4][2];
            #pragma unroll
            for (int nt = 0; nt < 4; nt++) {
                int cc = wn * 32 + nt * 8 + gid;
                int kr = kc * 8 + tig;
                bf[nt][0] = Bs[kr    ][cc];
                bf[nt][1] = Bs[kr + 4][cc];
            }
            #pragma unroll
            for (int mt = 0; mt < 4; mt++)
                #pragma unroll
                for (int nt = 0; nt < 4; nt++)
                    mma_tf32(acc[mt][nt], af[mt], bf[nt]);
        }
        __syncthreads();
        if (k0 < kend) {
            STORE_TILES();
            __syncthreads();
        }
    }

    // ---- epilogue ----
    #pragma unroll
    for (int nt = 0; nt < 4; nt++) {
        const int col = col0 + wn * 32 + nt * 8 + tig * 2;
        float bx = 0.f, by = 0.f;
        if (EPI != 3 && bias) { bx = bias[col]; by = bias[col + 1]; }
        #pragma unroll
        for (int mt = 0; mt < 4; mt++) {
            #pragma unroll
            for (int half = 0; half < 2; half++) {
                int r = row0 + wm * 64 + mt * 16 + gid + half * 8;
                if (r >= M) continue;
                float v0 = acc[mt][nt][half * 2 + 0] + bx;
                float v1 = acc[mt][nt][half * 2 + 1] + by;
                if (EPI == 1) {
                    v0 = v0 / (1.f + __expf(-v0));
                    v1 = v1 / (1.f + __expf(-v1));
                }
                if (EPI == 2) {
                    float2 rr = *(const float2*)(res + (size_t)r * N + col);
                    v0 += rr.x; v1 += rr.y;
                }
                *(float2*)(C + (size_t)r * N + col) = make_float2(v0, v1);
            }
        }
    }
    #undef LOAD_A
    #undef LOAD_B
    #undef STORE_TILES
}

// ---------------- conv split-K reduce: r = bias + sum_z partial[z] ------------
__global__ void conv_reduce(const float* __restrict__ part, const float* __restrict__ bias,
                            float* __restrict__ outb)
{
    int i = blockIdx.x * 256 + threadIdx.x;          // float4 index; total 75264
    const float4* p4 = (const float4*)part;
    float4 s = ((const float4*)bias)[i % (DIM / 4)];
    #pragma unroll
    for (int z = 0; z < CONV_SPLIT; z++) {
        float4 v = p4[(size_t)z * (CONV_M * DIM / 4) + i];
        s.x += v.x; s.y += v.y; s.z += v.z; s.w += v.w;
    }
    ((float4*)outb)[i] = s;
}

// ---------------- local window attention (scores bounded -> no running max) ---
__global__ void winattn_kernel(const float* __restrict__ qkv, float* __restrict__ out)
{
    const int blk = blockIdx.x;           // 784*12
    const int h   = blk % NHEAD;
    const int win = blk / NHEAD;
    const int bb  = win / 49;
    const int wq  = win % 49;
    const int hs  = wq / 7, ws = wq % 7;

    __shared__ float ks[64][32], vs[64][32];
    const int tid = threadIdx.x;          // 64 = one query per thread
    const int iy = tid >> 3, ix = tid & 7;
    const int tok = (bb * HH + hs * 8 + iy) * WW + ws * 8 + ix;
    const float* base = qkv + (size_t)tok * QKVD + h * DHEAD;

    float q[32];
    #pragma unroll
    for (int d4 = 0; d4 < 8; d4++) {
        float4 qv = *(const float4*)(base + d4 * 4);
        q[d4*4+0]=qv.x; q[d4*4+1]=qv.y; q[d4*4+2]=qv.z; q[d4*4+3]=qv.w;
        *(float4*)&ks[tid][d4*4] = *(const float4*)(base + 384 + d4 * 4);
        *(float4*)&vs[tid][d4*4] = *(const float4*)(base + 768 + d4 * 4);
    }
    __syncthreads();

    float ssum = 0.f, acc[32];
    #pragma unroll
    for (int d = 0; d < 32; d++) acc[d] = 0.f;

    for (int l = 0; l < 64; l++) {
        float s0=0.f, s1=0.f, s2=0.f, s3=0.f;
        #pragma unroll
        for (int d = 0; d < 32; d += 4) {
            s0 += q[d+0]*ks[l][d+0]; s1 += q[d+1]*ks[l][d+1];
            s2 += q[d+2]*ks[l][d+2]; s3 += q[d+3]*ks[l][d+3];
        }
        float p = __expf((s0+s1+s2+s3) * ATTN_SCALE);
        ssum += p;
        #pragma unroll
        for (int d = 0; d < 32; d++) acc[d] += p * vs[l][d];
    }
    float inv = 1.f / ssum;
    float* o = out + (size_t)tok * DIM + h * DHEAD;
    #pragma unroll
    for (int d4 = 0; d4 < 8; d4++) {
        float4 v;
        v.x = acc[d4*4+0]*inv; v.y = acc[d4*4+1]*inv;
        v.z = acc[d4*4+2]*inv; v.w = acc[d4*4+3]*inv;
        *(float4*)(o + d4 * 4) = v;
    }
}

// ---------------- global attention: block = (batch, head), K=49 in SMEM -------
__global__ void gattn_kernel(const float* __restrict__ q, const float* __restrict__ kv,
                             float* __restrict__ out)
{
    const int bb = blockIdx.x / NHEAD;
    const int h  = blockIdx.x % NHEAD;
    __shared__ float ks[49][32], vs[49][32];
    const int tid = threadIdx.x;          // 256

    for (int e = tid; e < 49 * 32; e += 256) {
        int l = e >> 5, d = e & 31;
        size_t r = ((size_t)(bb * LRED + l)) * (2 * DIM) + h * DHEAD + d;
        ks[l][d] = kv[r];
        vs[l][d] = kv[r + DIM];
    }
    __syncthreads();

    for (int qi = tid; qi < HW; qi += 256) {
        const int tok = bb * HW + qi;
        const float* qp = q + (size_t)tok * DIM + h * DHEAD;
        float qr[32];
        #pragma unroll
        for (int d4 = 0; d4 < 8; d4++) {
            float4 qv = *(const float4*)(qp + d4 * 4);
            qr[d4*4+0]=qv.x; qr[d4*4+1]=qv.y; qr[d4*4+2]=qv.z; qr[d4*4+3]=qv.w;
        }
        float ssum = 0.f, acc[32];
        #pragma unroll
        for (int d = 0; d < 32; d++) acc[d] = 0.f;

        for (int l = 0; l < 49; l++) {
            float s0=0.f, s1=0.f, s2=0.f, s3=0.f;
            #pragma unroll
            for (int d = 0; d < 32; d += 4) {
                s0 += qr[d+0]*ks[l][d+0]; s1 += qr[d+1]*ks[l][d+1];
                s2 += qr[d+2]*ks[l][d+2]; s3 += qr[d+3]*ks[l][d+3];
            }
            float p = __expf((s0+s1+s2+s3) * ATTN_SCALE);
            ssum += p;
            #pragma unroll
            for (int d = 0; d < 32; d++) acc[d] += p * vs[l][d];
        }
        float inv = 1.f / ssum;
        float* o = out + (size_t)tok * DIM + h * DHEAD;
        #pragma unroll
        for (int d4 = 0; d4 < 8; d4++) {
            float4 v;
            v.x = acc[d4*4+0]*inv; v.y = acc[d4*4+1]*inv;
            v.z = acc[d4*4+2]*inv; v.w = acc[d4*4+3]*inv;
            *(float4*)(o + d4 * 4) = v;
        }
    }
}

// ---------------- launch ----------------
static inline dim3 ggrid(int M, int N) { return dim3(N / 128, (M + 127) / 128); }

extern "C" void kernel_launch(void* const* d_in, const int* in_sizes, int n_in,
                              void* d_out, int out_size)
{
    const float* x      = (const float*)d_in[0];
    const float* g1     = (const float*)d_in[1];
    const float* be1    = (const float*)d_in[2];
    const float* w_qkv  = (const float*)d_in[3];
    const float* b_qkv  = (const float*)d_in[4];
    const float* w_lo   = (const float*)d_in[5];
    const float* b_lo   = (const float*)d_in[6];
    const float* g2     = (const float*)d_in[7];
    const float* be2    = (const float*)d_in[8];
    const float* w_f1l  = (const float*)d_in[9];
    const float* b_f1l  = (const float*)d_in[10];
    const float* w_f2l  = (const float*)d_in[11];
    const float* b_f2l  = (const float*)d_in[12];
    const float* g3     = (const float*)d_in[13];
    const float* be3    = (const float*)d_in[14];
    const float* w_q    = (const float*)d_in[15];
    const float* w_kv   = (const float*)d_in[16];
    const float* conv_w = (const float*)d_in[17];
    const float* conv_b = (const float*)d_in[18];
    const float* w_go   = (const float*)d_in[19];
    const float* b_go   = (const float*)d_in[20];
    const float* g4     = (const float*)d_in[21];
    const float* be4    = (const float*)d_in[22];
    const float* w_f1g  = (const float*)d_in[23];
    const float* b_f1g  = (const float*)d_in[24];
    const float* w_f2g  = (const float*)d_in[25];
    const float* b_f2g  = (const float*)d_in[26];
    float* out = (float*)d_out;

    float *p_ln, *p_big, *p_tmp, *p_q, *p_r, *p_kv, *p_rp;
    cudaGetSymbolAddress((void**)&p_ln,  g_ln);
    cudaGetSymbolAddress((void**)&p_big, g_big);
    cudaGetSymbolAddress((void**)&p_tmp, g_tmp);
    cudaGetSymbolAddress((void**)&p_q,   g_q);
    cudaGetSymbolAddress((void**)&p_r,   g_r);
    cudaGetSymbolAddress((void**)&p_kv,  g_kv);
    cudaGetSymbolAddress((void**)&p_rp,  g_rpart);

    // ---- block 1: local attention ----
    ln_kernel<<<NTOK / 8, 256>>>(x, g1, be1, p_ln, NTOK);
    gemm_tc<0,0><<<ggrid(NTOK, QKVD), 256>>>(p_ln, w_qkv, b_qkv, nullptr, p_big, NTOK, QKVD, DIM, 0);
    winattn_kernel<<<BATCH * 49 * NHEAD, 64>>>(p_big, p_tmp);
    gemm_tc<0,2><<<ggrid(NTOK, DIM), 256>>>(p_tmp, w_lo, b_lo, x, out, NTOK, DIM, DIM, 0);

    // ---- block 2: local FFN ----
    ln_kernel<<<NTOK / 8, 256>>>(out, g2, be2, p_ln, NTOK);
    gemm_tc<0,1><<<ggrid(NTOK, FFDIM), 256>>>(p_ln, w_f1l, b_f1l, nullptr, p_big, NTOK, FFDIM, DIM, 0);
    gemm_tc<0,2><<<ggrid(NTOK, DIM), 256>>>(p_big, w_f2l, b_f2l, out, out, NTOK, DIM, FFDIM, 0);

    // ---- block 3: global attention ----
    ln_kernel<<<NTOK / 8, 256>>>(out, g3, be3, p_ln, NTOK);
    gemm_tc<0,0><<<ggrid(NTOK, DIM), 256>>>(p_ln, w_q, nullptr, nullptr, p_q, NTOK, DIM, DIM, 0);
    // strided 8x8 conv as gather-GEMM, split-K x8 (deterministic partials)
    {
        dim3 cg(DIM / 128, (CONV_M + 127) / 128, CONV_SPLIT);
        gemm_tc<1,3><<<cg, 256>>>(p_ln, conv_w, nullptr, nullptr, p_rp,
                                  CONV_M, DIM, CONV_K, CONV_K / CONV_SPLIT);
        conv_reduce<<<(CONV_M * DIM / 4) / 256, 256>>>(p_rp, conv_b, p_r);
    }
    gemm_tc<0,0><<<ggrid(CONV_M, 2 * DIM), 256>>>(p_r, w_kv, nullptr, nullptr, p_kv,
                                                  CONV_M, 2 * DIM, DIM, 0);
    gattn_kernel<<<BATCH * NHEAD, 256>>>(p_q, p_kv, p_tmp);
    gemm_tc<0,2><<<ggrid(NTOK, DIM), 256>>>(p_tmp, w_go, b_go, out, out, NTOK, DIM, DIM, 0);

    // ---- block 4: global FFN ----
    ln_kernel<<<NTOK / 8, 256>>>(out, g4, be4, p_ln, NTOK);
    gemm_tc<0,1><<<ggrid(NTOK, FFDIM), 256>>>(p_ln, w_f1g, b_f1g, nullptr, p_big, NTOK, FFDIM, DIM, 0);
    gemm_tc<0,2><<<ggrid(NTOK, DIM), 256>>>(p_big, w_f2g, b_f2g, out, out, NTOK, DIM, FFDIM, 0);
}